// round 11
// baseline (speedup 1.0000x reference)
#include <cuda_runtime.h>
#include <cuda_bf16.h>
#include <math.h>
#include <stdint.h>

#define Bz 32
#define Lz 768
#define Dz 256
#define Fz 256
#define Tz 3072

#define NCONV 192                       // conv tile CTAs per layer (M=128)
// fused grid block ranges
#define BLK_CS   NCONV                  // 32 cumsum
#define BLK_C2   (BLK_CS + Bz)          // 192 conv2 tiles
#define BLK_GA   (BLK_C2 + NCONV)       // 1536 gather
#define BLK_TOTAL (BLK_GA + 48 * Bz)    // 1952

// prep_all dispatch ranges
#define PREP_X_BLOCKS 3072
#define PREP_W_BLOCKS 768
#define PREP_TOTAL (PREP_X_BLOCKS + PREP_W_BLOCKS + 1)   // 3841

#define NFLAGS (NCONV + Bz)

// ---------------------------------------------------------------------------
// Scratch (allocation-free: __device__ globals)
// ---------------------------------------------------------------------------
__device__ __nv_bfloat16 g_xhi[Bz * Lz * Dz];
__device__ __nv_bfloat16 g_xlo[Bz * Lz * Dz];
__device__ __nv_bfloat16 g_h1h[Bz * Lz * Fz];
__device__ __nv_bfloat16 g_h1l[Bz * Lz * Fz];
__device__ uint32_t g_w1ph[3 * 256 * 128];
__device__ uint32_t g_w1pl[3 * 256 * 128];
__device__ uint32_t g_w2ph[3 * 256 * 128];
__device__ uint32_t g_w2pl[3 * 256 * 128];
__device__ float    g_glw[256];
__device__ float    g_scal[2];
__device__ int      g_cum[Bz * Lz];
__device__ int      g_flag[NFLAGS];

// ---------------------------------------------------------------------------
// helpers
// ---------------------------------------------------------------------------
__device__ __forceinline__ uint32_t smem_u32(const void* p) {
    uint32_t a;
    asm("{ .reg .u64 t; cvta.to.shared.u64 t, %1; cvt.u32.u64 %0, t; }"
        : "=r"(a) : "l"(p));
    return a;
}

__device__ __forceinline__ void cp16(uint32_t dst, const void* src, int src_bytes) {
    asm volatile("cp.async.cg.shared.global [%0], [%1], 16, %2;"
                 :: "r"(dst), "l"(src), "r"(src_bytes) : "memory");
}
#define CP_COMMIT() asm volatile("cp.async.commit_group;" ::: "memory")
#define CP_WAIT(n)  asm volatile("cp.async.wait_group %0;" :: "n"(n) : "memory")

#define LDSM_X4(r, addr) \
    asm volatile("ldmatrix.sync.aligned.m8n8.x4.shared.b16 {%0,%1,%2,%3}, [%4];" \
        : "=r"((r)[0]), "=r"((r)[1]), "=r"((r)[2]), "=r"((r)[3]) : "r"(addr))

__device__ __forceinline__ void mma16816(float* c, const uint32_t* a,
                                         uint32_t b0, uint32_t b1)
{
    asm("mma.sync.aligned.m16n8k16.row.col.f32.bf16.bf16.f32 "
        "{%0,%1,%2,%3}, {%4,%5,%6,%7}, {%8,%9}, {%0,%1,%2,%3};\n"
        : "+f"(c[0]), "+f"(c[1]), "+f"(c[2]), "+f"(c[3])
        : "r"(a[0]), "r"(a[1]), "r"(a[2]), "r"(a[3]), "r"(b0), "r"(b1));
}

__device__ __forceinline__ void split2(float a, float b, uint32_t& hi, uint32_t& lo)
{
    __nv_bfloat162 h = __floats2bfloat162_rn(a, b);
    float ra = a - __bfloat162float(h.x);
    float rb = b - __bfloat162float(h.y);
    __nv_bfloat162 l = __floats2bfloat162_rn(ra, rb);
    hi = *(uint32_t*)&h;
    lo = *(uint32_t*)&l;
}

__device__ __forceinline__ void flag_publish(int idx) {
    __threadfence();
    if (threadIdx.x == 0) atomicExch(&g_flag[idx], 1);
}
__device__ __forceinline__ void flag_spin(int idx) {
    if (threadIdx.x == 0) {
        while (atomicAdd(&g_flag[idx], 0) == 0) __nanosleep(64);
    }
}

// ---------------------------------------------------------------------------
// Unified prep kernel (256 threads/block)
// ---------------------------------------------------------------------------
__global__ __launch_bounds__(256)
void prep_all(const float* __restrict__ x,
              __nv_bfloat16* __restrict__ ohi, __nv_bfloat16* __restrict__ olo,
              const float* __restrict__ w1, const float* __restrict__ w2,
              uint32_t* __restrict__ p1h, uint32_t* __restrict__ p1l,
              uint32_t* __restrict__ p2h, uint32_t* __restrict__ p2l,
              const float* __restrict__ g, const float* __restrict__ bb,
              const float* __restrict__ lw, const float* __restrict__ lb,
              float* __restrict__ glw, float* __restrict__ scal)
{
    const int blk = blockIdx.x;
    const int t = threadIdx.x;

    if (blk < PREP_X_BLOCKS) {
        size_t i = ((size_t)blk * 256 + t) * 8;
        float4 f0 = *(const float4*)(x + i);
        float4 f1 = *(const float4*)(x + i + 4);
        uint4 vh, vl;
        split2(f0.x, f0.y, vh.x, vl.x);
        split2(f0.z, f0.w, vh.y, vl.y);
        split2(f1.x, f1.y, vh.z, vl.z);
        split2(f1.z, f1.w, vh.w, vl.w);
        *(uint4*)(ohi + i) = vh;
        *(uint4*)(olo + i) = vl;
        return;
    }
    if (blk < PREP_X_BLOCKS + PREP_W_BLOCKS) {
        int e = blk - PREP_X_BLOCKS;
        int sel = e >= 384;
        int idx = (e - sel * 384) * 256 + t;
        const float* w = sel ? w2 : w1;
        uint32_t* ph = sel ? p2h : p1h;
        uint32_t* pl = sel ? p2l : p1l;
        int p   = idx & 127;
        int n   = (idx >> 7) & 255;
        int tap = idx >> 15;
        float a = w[((size_t)(tap * 256 + 2 * p))     * 256 + n];
        float b = w[((size_t)(tap * 256 + 2 * p + 1)) * 256 + n];
        uint32_t hi, lo;
        split2(a, b, hi, lo);
        ph[idx] = hi;
        pl[idx] = lo;
        return;
    }
    // scalars + flag reset
    {
        for (int i = t; i < NFLAGS; i += 256) g_flag[i] = 0;
        __shared__ float sg[8], sb[8];
        float lwv = lw[t];
        float gv = g[t] * lwv;
        float bv = bb[t] * lwv;
        glw[t] = gv;
#pragma unroll
        for (int o = 16; o; o >>= 1) {
            gv += __shfl_xor_sync(0xffffffffu, gv, o);
            bv += __shfl_xor_sync(0xffffffffu, bv, o);
        }
        if ((t & 31) == 0) { sg[t >> 5] = gv; sb[t >> 5] = bv; }
        __syncthreads();
        if (t == 0) {
            float G = 0.f, Bv = 0.f;
            for (int i = 0; i < 8; i++) { G += sg[i]; Bv += sb[i]; }
            scal[0] = G;
            scal[1] = Bv + lb[0];
        }
    }
}

// ---------------------------------------------------------------------------
// cumsum for one batch (512-thread block; threads 0..255 active)
// ---------------------------------------------------------------------------
__device__ void cumsum_block(int b, const int* __restrict__ target,
                             float* __restrict__ dpo_out, char* smem)
{
    int* ps = (int*)smem;
    const int t = threadIdx.x;
    int v0 = 0, v1 = 0, v2 = 0, s1 = 0, s2 = 0;
    const size_t base = (size_t)b * Lz + 3 * t;
    if (t < 256) {
        v0 = target[base]; v1 = target[base + 1]; v2 = target[base + 2];
        s1 = v0 + v1; s2 = s1 + v2;
        ps[t] = s2;
    }
    __syncthreads();
#pragma unroll
    for (int off = 1; off < 256; off <<= 1) {
        int u = (t >= off && t < 256) ? ps[t - off] : 0;
        __syncthreads();
        if (t < 256) ps[t] += u;
        __syncthreads();
    }
    if (t < 256) {
        int pre = (t > 0) ? ps[t - 1] : 0;
        g_cum[base]     = pre + v0;
        g_cum[base + 1] = pre + s1;
        g_cum[base + 2] = pre + s2;
        dpo_out[base]     = (float)v0;
        dpo_out[base + 1] = (float)v1;
        dpo_out[base + 2] = (float)v2;
    }
    flag_publish(NCONV + b);
}

// ---------------------------------------------------------------------------
// gather for one (batch, 64-t block), 512 threads: 8 tlocs x 64 subs
// ---------------------------------------------------------------------------
__device__ void gather_block(int e, const float* __restrict__ x,
                             float* __restrict__ dout, char* smem)
{
    int* cum = (int*)smem;
    const int b = e / 48;
    const int tpart = e % 48;
    const int tid = threadIdx.x;

    flag_spin(NCONV + b);
    __syncthreads();

    for (int i = tid; i < Lz; i += 512)
        cum[i] = g_cum[(size_t)b * Lz + i];
    __syncthreads();

    const int total = cum[Lz - 1];
    const int t0 = tpart * 64;
    const int sub  = tid & 63;
    const int tloc = tid >> 6;   // 0..7

    const float4* xrow = (const float4*)(x + (size_t)b * Lz * Dz);
    float4* orow = (float4*)(dout + (size_t)b * Tz * Dz);

#pragma unroll
    for (int it = 0; it < 8; ++it) {
        int t = t0 + it * 8 + tloc;
        int lo = 0, hi = Lz;
        while (lo < hi) {
            int mid = (lo + hi) >> 1;
            if (cum[mid] <= t) lo = mid + 1; else hi = mid;
        }
        float4 v;
        if (t < total) {
            int idx = min(lo, Lz - 1);
            v = xrow[(size_t)idx * 64 + sub];
        } else {
            v = make_float4(0.0f, 0.0f, 0.0f, 0.0f);
        }
        orow[(size_t)t * 64 + sub] = v;
    }
}

// ---------------------------------------------------------------------------
// conv tile body: M=128 x N=256, 512 threads (16 warps 4M x 4N), 3-stage
// cp.async pipeline, ONE barrier per chunk.
// ---------------------------------------------------------------------------
#define SA_H 0
#define SA_L 10240
#define SB_H 20480
#define SB_L 40960
#define STAGE 61440
#define STAGE0_OFF 4096
#define CONV_SMEM (STAGE0_OFF + 3 * STAGE)   // 188416

__device__ __forceinline__ void load_chunk(
    uint32_t stg, int c, int tid, int l0, size_t rowbase,
    const __nv_bfloat16* __restrict__ Ahi, const __nv_bfloat16* __restrict__ Alo,
    const uint32_t* __restrict__ Wph, const uint32_t* __restrict__ Wpl)
{
    const int tap  = c >> 3;
    const int cin0 = (c & 7) << 5;
    // A: 128 rows x 64B (4 segs of 16B); one (row,seg) per thread
    {
        int row = tid >> 2, seg = tid & 3;
        int gl = l0 + row + tap - 1;
        int ok = (gl >= 0 && gl < Lz) ? 16 : 0;
        int glc = gl < 0 ? 0 : (gl >= Lz ? Lz - 1 : gl);
        size_t off = ((rowbase + glc) << 8) + cin0 + (seg << 3);
        uint32_t d = row * 80 + seg * 16;
        cp16(stg + SA_H + d, Ahi + off, ok);
        cp16(stg + SA_L + d, Alo + off, ok);
    }
    // B: 256 n x 16 pairs u32 (4 segs of 16B per n); 2 per thread
    const int p0 = (c & 7) << 4;
    const uint32_t* bh = Wph + (size_t)tap * 256 * 128 + p0;
    const uint32_t* bl = Wpl + (size_t)tap * 256 * 128 + p0;
#pragma unroll
    for (int i = 0; i < 2; ++i) {
        int idx = tid + (i << 9);            // 0..1023
        int n = idx >> 2, seg = idx & 3;
        uint32_t d = n * 80 + seg * 16;
        cp16(stg + SB_H + d, bh + n * 128 + seg * 4, 16);
        cp16(stg + SB_L + d, bl + n * 128 + seg * 4, 16);
    }
}

__device__ void conv_tile(
    int tile, bool fin, char* smem,
    const __nv_bfloat16* __restrict__ Ahi, const __nv_bfloat16* __restrict__ Alo,
    const uint32_t* __restrict__ Wph, const uint32_t* __restrict__ Wpl,
    const float* __restrict__ bias, const float* __restrict__ gamma,
    const float* __restrict__ beta, const float* __restrict__ glw,
    const float* __restrict__ scal,
    __nv_bfloat16* __restrict__ outhi, __nv_bfloat16* __restrict__ outlo,
    float* __restrict__ dur)
{
    const uint32_t sb = smem_u32(smem);
    float* svec = (float*)smem;                       // [4][256]
    const uint32_t stage0 = sb + STAGE0_OFF;

    const int tid = threadIdx.x;
    const int wid = tid >> 5, lane = tid & 31;
    const int wm = wid >> 2, wn = wid & 3;            // 4M x 4N warps
    const int grp = lane >> 2, tig = lane & 3;

    const int batch = tile / 6;
    const int part  = tile % 6;
    const int l0 = part * 128;
    const size_t rowbase = (size_t)batch * Lz;

    if (fin) {
        flag_spin(tile);
        if (part > 0) flag_spin(tile - 1);
        if (part < 5) flag_spin(tile + 1);
        __threadfence();
    }
    __syncthreads();

    if (tid < 256) {
        svec[tid]       = bias[tid];
        svec[256 + tid] = gamma[tid];
        svec[512 + tid] = beta[tid];
        svec[768 + tid] = fin ? glw[tid] : 0.f;
    }

    const uint32_t a_off = (uint32_t)((wm * 32 + (lane & 15)) * 80 + (lane >> 4) * 16);
    const uint32_t b_row = (uint32_t)(wn * 64 + ((lane & 7) | ((lane >> 4) << 3)));
    const uint32_t b_off = b_row * 80 + (((lane >> 3) & 1) * 16);

    float acc[2][8][4];
#pragma unroll
    for (int mt = 0; mt < 2; mt++)
#pragma unroll
        for (int nt = 0; nt < 8; nt++)
#pragma unroll
            for (int i = 0; i < 4; i++) acc[mt][nt][i] = 0.f;

    // prologue: 2 chunks in flight
    load_chunk(stage0,         0, tid, l0, rowbase, Ahi, Alo, Wph, Wpl);
    CP_COMMIT();
    load_chunk(stage0 + STAGE, 1, tid, l0, rowbase, Ahi, Alo, Wph, Wpl);
    CP_COMMIT();

    int stg_idx = 0;
    for (int c = 0; c < 24; ++c) {
        const uint32_t stg = stage0 + stg_idx * STAGE;
        if (c < 23) CP_WAIT(1); else CP_WAIT(0);
        __syncthreads();   // stage c ready for all; stage (c+2)%3 free for all

        // issue loads for c+2 immediately (lands while computing c and c+1)
        if (c + 2 < 24) {
            int nidx = stg_idx + 2; if (nidx >= 3) nidx -= 3;
            load_chunk(stage0 + nidx * STAGE, c + 2, tid, l0, rowbase, Ahi, Alo, Wph, Wpl);
            CP_COMMIT();
        }

#pragma unroll
        for (int kt = 0; kt < 2; ++kt) {
            uint32_t ah[2][4], al[2][4];
#pragma unroll
            for (int mt = 0; mt < 2; ++mt) {
                LDSM_X4(ah[mt], stg + SA_H + a_off + mt * (16 * 80) + kt * 32);
                LDSM_X4(al[mt], stg + SA_L + a_off + mt * (16 * 80) + kt * 32);
            }
#pragma unroll
            for (int j = 0; j < 4; ++j) {
                uint32_t bh[4], bl[4];
                LDSM_X4(bh, stg + SB_H + b_off + j * (16 * 80) + kt * 32);
                LDSM_X4(bl, stg + SB_L + b_off + j * (16 * 80) + kt * 32);
#pragma unroll
                for (int h = 0; h < 2; ++h)
#pragma unroll
                    for (int mt = 0; mt < 2; ++mt)
                        mma16816(acc[mt][j * 2 + h], ah[mt], bh[h * 2], bh[h * 2 + 1]);
#pragma unroll
                for (int h = 0; h < 2; ++h)
#pragma unroll
                    for (int mt = 0; mt < 2; ++mt)
                        mma16816(acc[mt][j * 2 + h], al[mt], bh[h * 2], bh[h * 2 + 1]);
#pragma unroll
                for (int h = 0; h < 2; ++h)
#pragma unroll
                    for (int mt = 0; mt < 2; ++mt)
                        mma16816(acc[mt][j * 2 + h], ah[mt], bl[h * 2], bl[h * 2 + 1]);
            }
        }
        if (++stg_idx == 3) stg_idx = 0;
    }
    __syncthreads();   // stage region free -> epilogue overlay

    // ----- epilogue -----
    float* pa  = (float*)(smem + STAGE0_OFF);     // [3][128][4]
    float* smu = pa + 3 * 128 * 4;                // [128]
    float* srs = smu + 128;                       // [128]

#pragma unroll
    for (int mt = 0; mt < 2; ++mt)
#pragma unroll
        for (int hf = 0; hf < 2; ++hf) {
            float s = 0.f, sq = 0.f, sd = 0.f;
#pragma unroll
            for (int nt = 0; nt < 8; ++nt) {
                int col = wn * 64 + nt * 8 + 2 * tig;
                float v0 = fmaxf(acc[mt][nt][hf * 2 + 0] + svec[col], 0.f);
                float v1 = fmaxf(acc[mt][nt][hf * 2 + 1] + svec[col + 1], 0.f);
                acc[mt][nt][hf * 2 + 0] = v0;
                acc[mt][nt][hf * 2 + 1] = v1;
                s += v0 + v1;
                sq += v0 * v0 + v1 * v1;
                if (fin) sd += v0 * svec[768 + col] + v1 * svec[768 + col + 1];
            }
            s  += __shfl_xor_sync(0xffffffffu, s, 1);
            s  += __shfl_xor_sync(0xffffffffu, s, 2);
            sq += __shfl_xor_sync(0xffffffffu, sq, 1);
            sq += __shfl_xor_sync(0xffffffffu, sq, 2);
            if (fin) {
                sd += __shfl_xor_sync(0xffffffffu, sd, 1);
                sd += __shfl_xor_sync(0xffffffffu, sd, 2);
            }
            if (tig == 0) {
                int row = wm * 32 + mt * 16 + hf * 8 + grp;
                pa[0 * 512 + row * 4 + wn] = s;
                pa[1 * 512 + row * 4 + wn] = sq;
                if (fin) pa[2 * 512 + row * 4 + wn] = sd;
            }
        }
    __syncthreads();

    if (tid < 128) {
        int row = tid;
        float s  = pa[row * 4] + pa[row * 4 + 1] + pa[row * 4 + 2] + pa[row * 4 + 3];
        float sq = pa[512 + row * 4] + pa[512 + row * 4 + 1] +
                   pa[512 + row * 4 + 2] + pa[512 + row * 4 + 3];
        float mu  = s * (1.f / 256.f);
        float var = sq * (1.f / 256.f) - mu * mu;
        float rs  = rsqrtf(var + 1e-5f);
        if (fin) {
            float s3 = pa[1024 + row * 4] + pa[1024 + row * 4 + 1] +
                       pa[1024 + row * 4 + 2] + pa[1024 + row * 4 + 3];
            dur[(size_t)tile * 128 + row] = expf(rs * (s3 - mu * scal[0]) + scal[1]);
        } else {
            smu[row] = mu;
            srs[row] = rs;
        }
    }

    if (!fin) {
        __syncthreads();
#pragma unroll
        for (int mt = 0; mt < 2; ++mt)
#pragma unroll
            for (int hf = 0; hf < 2; ++hf) {
                int row = wm * 32 + mt * 16 + hf * 8 + grp;
                float mu = smu[row], rs = srs[row];
#pragma unroll
                for (int nt = 0; nt < 8; ++nt) {
                    int col = wn * 64 + nt * 8 + 2 * tig;
                    float v0 = (acc[mt][nt][hf * 2 + 0] - mu) * rs * svec[256 + col]     + svec[512 + col];
                    float v1 = (acc[mt][nt][hf * 2 + 1] - mu) * rs * svec[256 + col + 1] + svec[512 + col + 1];
                    uint32_t hi, lo;
                    split2(v0, v1, hi, lo);
                    size_t off = ((size_t)tile * 128 + row) * 256 + col;
                    *(uint32_t*)(outhi + off) = hi;
                    *(uint32_t*)(outlo + off) = lo;
                }
            }
        flag_publish(tile);
    }
}

// ---------------------------------------------------------------------------
// Fused pipeline kernel: conv1 | cumsum | conv2(+lin+exp) | gather
// ---------------------------------------------------------------------------
__global__ void __launch_bounds__(512, 1)
fused_all(const __nv_bfloat16* __restrict__ xhi, const __nv_bfloat16* __restrict__ xlo,
          __nv_bfloat16* __restrict__ h1h, __nv_bfloat16* __restrict__ h1l,
          const uint32_t* __restrict__ w1ph, const uint32_t* __restrict__ w1pl,
          const uint32_t* __restrict__ w2ph, const uint32_t* __restrict__ w2pl,
          const float* __restrict__ conv1_b, const float* __restrict__ ln1_g,
          const float* __restrict__ ln1_b,
          const float* __restrict__ conv2_b, const float* __restrict__ ln2_g,
          const float* __restrict__ ln2_b,
          const float* __restrict__ glw, const float* __restrict__ scal,
          const int* __restrict__ target, const float* __restrict__ x,
          float* __restrict__ out_gather, float* __restrict__ out_dpo,
          float* __restrict__ out_dur)
{
    extern __shared__ char smem[];
    const int blk = blockIdx.x;

    if (blk < BLK_CS) {
        conv_tile(blk, false, smem, xhi, xlo, w1ph, w1pl,
                  conv1_b, ln1_g, ln1_b, glw, scal, h1h, h1l, nullptr);
    } else if (blk < BLK_C2) {
        cumsum_block(blk - BLK_CS, target, out_dpo, smem);
    } else if (blk < BLK_GA) {
        conv_tile(blk - BLK_C2, true, smem, h1h, h1l, w2ph, w2pl,
                  conv2_b, ln2_g, ln2_b, glw, scal, nullptr, nullptr, out_dur);
    } else {
        gather_block(blk - BLK_GA, x, out_gather, smem);
    }
}

// ---------------------------------------------------------------------------
// Launch
// ---------------------------------------------------------------------------
extern "C" void kernel_launch(void* const* d_in, const int* in_sizes, int n_in,
                              void* d_out, int out_size)
{
    const float* x       = (const float*)d_in[0];
    const int*   target  = (const int*)  d_in[1];
    const float* conv1_w = (const float*)d_in[3];
    const float* conv1_b = (const float*)d_in[4];
    const float* ln1_g   = (const float*)d_in[5];
    const float* ln1_b   = (const float*)d_in[6];
    const float* conv2_w = (const float*)d_in[7];
    const float* conv2_b = (const float*)d_in[8];
    const float* ln2_g   = (const float*)d_in[9];
    const float* ln2_b   = (const float*)d_in[10];
    const float* lin_w   = (const float*)d_in[11];
    const float* lin_b   = (const float*)d_in[12];

    float* out_gather = (float*)d_out;                        // [B, T, D]
    float* out_dpo    = out_gather + (size_t)Bz * Tz * Dz;    // [B, L]
    float* out_dur    = out_dpo + (size_t)Bz * Lz;            // [B, L]

    __nv_bfloat16 *xhi, *xlo, *h1h, *h1l;
    uint32_t *w1ph, *w1pl, *w2ph, *w2pl;
    float *glw, *scal;
    cudaGetSymbolAddress((void**)&xhi,  g_xhi);
    cudaGetSymbolAddress((void**)&xlo,  g_xlo);
    cudaGetSymbolAddress((void**)&h1h,  g_h1h);
    cudaGetSymbolAddress((void**)&h1l,  g_h1l);
    cudaGetSymbolAddress((void**)&w1ph, g_w1ph);
    cudaGetSymbolAddress((void**)&w1pl, g_w1pl);
    cudaGetSymbolAddress((void**)&w2ph, g_w2ph);
    cudaGetSymbolAddress((void**)&w2pl, g_w2pl);
    cudaGetSymbolAddress((void**)&glw,  g_glw);
    cudaGetSymbolAddress((void**)&scal, g_scal);

    cudaFuncSetAttribute(fused_all, cudaFuncAttributeMaxDynamicSharedMemorySize, CONV_SMEM);

    // Prep: x split | weight repack | scalars + flag reset
    prep_all<<<PREP_TOTAL, 256>>>(x, xhi, xlo, conv1_w, conv2_w,
                                  w1ph, w1pl, w2ph, w2pl,
                                  ln2_g, ln2_b, lin_w, lin_b, glw, scal);

    // One fused pipeline kernel
    fused_all<<<BLK_TOTAL, 512, CONV_SMEM>>>(
        xhi, xlo, h1h, h1l,
        w1ph, w1pl, w2ph, w2pl,
        conv1_b, ln1_g, ln1_b, conv2_b, ln2_g, ln2_b,
        glw, scal, target, x, out_gather, out_dpo, out_dur);
}